// round 6
// baseline (speedup 1.0000x reference)
#include <cuda_runtime.h>
#include <cuda_fp16.h>
#include <math.h>
#include <stdint.h>

#define T_SEQ 20
#define NF    812
#define HID   400
#define NG    1600            // 4*HID
#define NGP   1664            // padded N (13*128)
#define BATCH 8192
#define MROWS (BATCH * T_SEQ) // 163840
#define KP    832             // per-section K big GEMM (26*32)
#define K2    (2 * KP)        // 1664: [hi(V), lo(V)] exact split
#define KH2   832             // gates K: [hi(400), lo(400), pad 32]
#define NCBIG (K2 / 32)       // 52
#define NCGAT (KH2 / 32)      // 26
#define NBT   (NGP / 128)     // 13 n-tiles

// ---------------- device scratch ----------------
__device__ __half g_V2[(size_t)MROWS * K2];          // ~545 MB split values
__device__ __half g_W2[(size_t)NGP * K2];            // W_ih [hi,hi] perm rows (pad rows 0)
__device__ __half g_Wh2[(size_t)NGP * KH2];          // W_hh [hi,hi] perm rows (pad rows 0)
__device__ __half g_h2[2][(size_t)BATCH * KH2];      // [hi(h), lo(h)] decayed h (dbl buf)
__device__ float g_G0[(size_t)MROWS * NGP];          // ~1.09 GB perm gate pre-acts
__device__ float g_c [BATCH * HID];
__device__ float g_xh_part[2][NBT][BATCH];           // per-bn regression partials (dbl buf)
__device__ float g_wsum[HID];
__device__ float g_num[T_SEQ];
__device__ float g_den[T_SEQ];

// ---------------- PTX helpers ----------------
__device__ __forceinline__ uint32_t smem_u32(const void* p) {
    uint32_t a;
    asm("{ .reg .u64 t; cvta.to.shared.u64 t, %1; cvt.u32.u64 %0, t; }" : "=r"(a) : "l"(p));
    return a;
}
__device__ __forceinline__ void cp_async16(uint32_t saddr, const void* gaddr) {
    asm volatile("cp.async.cg.shared.global [%0], [%1], 16;\n" :: "r"(saddr), "l"(gaddr) : "memory");
}
__device__ __forceinline__ void ldsm_x4(uint32_t* r, uint32_t addr) {
    asm volatile("ldmatrix.sync.aligned.m8n8.x4.shared.b16 {%0,%1,%2,%3}, [%4];"
                 : "=r"(r[0]), "=r"(r[1]), "=r"(r[2]), "=r"(r[3]) : "r"(addr));
}
__device__ __forceinline__ void mma16816(float* d, const uint32_t* a, const uint32_t* b) {
    asm volatile(
        "mma.sync.aligned.m16n8k16.row.col.f32.f16.f16.f32 "
        "{%0,%1,%2,%3}, {%4,%5,%6,%7}, {%8,%9}, {%0,%1,%2,%3};"
        : "+f"(d[0]), "+f"(d[1]), "+f"(d[2]), "+f"(d[3])
        : "r"(a[0]), "r"(a[1]), "r"(a[2]), "r"(a[3]), "r"(b[0]), "r"(b[1]));
}

// smem: A 128 rows x 32 halves (80B stride), B 128 rows x 32 halves
#define A_STRIDE_B 80
#define A_TILE_B   (128 * A_STRIDE_B)    // 10240
#define BUF_B      (2 * A_TILE_B)        // 20480 per stage
#define SMEM_DYN   40960                 // 2 stages; epilogue stage 128*66*4=33792 fits

// ---------------- mma mainloop (BM=128, BN=128, BK=32, 8 warps 4x2) ----------------
__device__ __forceinline__ void gemm_mainloop(
    const __half* Abase, const __half* Bbase,
    int aStride, int bStride, int nChunks,
    uint32_t sbuf, float acc[2][8][4], int tid)
{
    int lane = tid & 31, w = tid >> 5;
    int wm = w & 3, wn = w >> 2;
    uint32_t aOff = (uint32_t)((wm * 32 + (lane & 15)) * A_STRIDE_B + ((lane >> 4) << 4));
    uint32_t bWarp = (uint32_t)(A_TILE_B +
        (wn * 64 + ((lane >> 4) << 3) + (lane & 7)) * A_STRIDE_B + (((lane >> 3) & 1) << 4));

    int lrow = tid >> 2, lseg = tid & 3;

    {   // preload chunk 0 -> buf 0
        #pragma unroll
        for (int hh = 0; hh < 2; hh++) {
            int row = lrow + hh * 64;
            cp_async16(sbuf + row * A_STRIDE_B + lseg * 16,
                       Abase + (size_t)row * aStride + lseg * 8);
            cp_async16(sbuf + A_TILE_B + row * A_STRIDE_B + lseg * 16,
                       Bbase + (size_t)row * bStride + lseg * 8);
        }
        asm volatile("cp.async.commit_group;\n" ::: "memory");
    }

    for (int c = 0; c < nChunks; c++) {
        if (c + 1 < nChunks) {
            uint32_t dst = sbuf + ((c + 1) & 1) * BUF_B;
            int koff = (c + 1) * 32;
            #pragma unroll
            for (int hh = 0; hh < 2; hh++) {
                int row = lrow + hh * 64;
                cp_async16(dst + row * A_STRIDE_B + lseg * 16,
                           Abase + (size_t)row * aStride + koff + lseg * 8);
                cp_async16(dst + A_TILE_B + row * A_STRIDE_B + lseg * 16,
                           Bbase + (size_t)row * bStride + koff + lseg * 8);
            }
            asm volatile("cp.async.commit_group;\n" ::: "memory");
            asm volatile("cp.async.wait_group 1;\n" ::: "memory");
        } else {
            asm volatile("cp.async.wait_group 0;\n" ::: "memory");
        }
        __syncthreads();

        uint32_t cur = sbuf + (c & 1) * BUF_B;
        #pragma unroll
        for (int kc = 0; kc < 2; kc++) {
            uint32_t a0[4], a1[4], b[4][4];
            ldsm_x4(a0, cur + aOff + kc * 32);
            ldsm_x4(a1, cur + aOff + 16 * A_STRIDE_B + kc * 32);
            ldsm_x4(b[0], cur + bWarp + kc * 32);
            ldsm_x4(b[1], cur + bWarp + 16 * A_STRIDE_B + kc * 32);
            ldsm_x4(b[2], cur + bWarp + 32 * A_STRIDE_B + kc * 32);
            ldsm_x4(b[3], cur + bWarp + 48 * A_STRIDE_B + kc * 32);
            #pragma unroll
            for (int ni = 0; ni < 8; ni++) {
                mma16816(acc[0][ni], a0, &b[ni >> 1][(ni & 1) * 2]);
                mma16816(acc[1][ni], a1, &b[ni >> 1][(ni & 1) * 2]);
            }
        }
        __syncthreads();
    }
}

// stage one 64-col pass (warps with wn==nh) -> smem fp32 [128][66]
__device__ __forceinline__ void stage_pass(float* stage, float acc[2][8][4], int lane, int wm) {
    #pragma unroll
    for (int mi = 0; mi < 2; mi++)
        #pragma unroll
        for (int ni = 0; ni < 8; ni++) {
            int r0 = wm * 32 + mi * 16 + (lane >> 2);
            int cc = ni * 8 + (lane & 3) * 2;
            *(float2*)&stage[r0 * 66 + cc]       = make_float2(acc[mi][ni][0], acc[mi][ni][1]);
            *(float2*)&stage[(r0 + 8) * 66 + cc] = make_float2(acc[mi][ni][2], acc[mi][ni][3]);
        }
}

// ---------------- init ----------------
__global__ void k_init() {
    long i = (long)blockIdx.x * blockDim.x + threadIdx.x;
    long stride = (long)gridDim.x * blockDim.x;
    for (long p = i; p < (long)BATCH * HID; p += stride) g_c[p] = 0.f;
    for (long p = i; p < 2L * BATCH * KH2; p += stride) ((__half*)g_h2)[p] = __float2half(0.f);
    for (long p = i; p < 2L * NBT * BATCH; p += stride) ((float*)g_xh_part)[p] = 0.f;
    if (i < T_SEQ) { g_num[i] = 0.f; g_den[i] = 0.f; }
}

// ---------------- w_sum ----------------
__global__ void k_wsum(const float* __restrict__ Wd) {
    int row = blockIdx.x;
    __shared__ float red[256];
    float s = 0.f;
    for (int k = threadIdx.x; k < NF; k += 256) s += Wd[(size_t)row * NF + k];
    red[threadIdx.x] = s;
    __syncthreads();
    for (int off = 128; off; off >>= 1) {
        if (threadIdx.x < off) red[threadIdx.x] += red[threadIdx.x + off];
        __syncthreads();
    }
    if (threadIdx.x == 0) g_wsum[row] = red[0];
}

// ---------------- V2 = [hi(V), lo(V)] (exact split) ----------------
__global__ void k_convV(const float* __restrict__ V) {
    int r = blockIdx.x;
    const float* src = V + (size_t)r * NF;
    __half* dst = g_V2 + (size_t)r * K2;
    for (int k = threadIdx.x; k < KP; k += 256) {
        float v = (k < NF) ? src[k] : 0.f;
        __half hi = __float2half_rn(v);
        __half lo = __float2half_rn(v - __half2float(hi));
        dst[k] = hi; dst[KP + k] = lo;
    }
}

// ---------------- W2 rows permuted (n = j*4+g), [hi, hi]; pad rows 0 ----------------
__global__ void k_convW(const float* __restrict__ Wih) {
    int n = blockIdx.x;                     // 0..NGP-1
    int orig = (n < NG) ? ((n & 3) * HID + (n >> 2)) : 0;
    __half* dst = g_W2 + (size_t)n * K2;
    const float* src = Wih + (size_t)orig * (NF + 1);
    for (int k = threadIdx.x; k < KP; k += 256) {
        float w = (n < NG && k < NF) ? src[k] : 0.f;
        __half hi = __float2half_rn(w);
        dst[k] = hi; dst[KP + k] = hi;
    }
}

// ---------------- Wh2 rows permuted, [hi(400), hi(400), pad 0] ----------------
__global__ void k_convWh(const float* __restrict__ Whh) {
    int n = blockIdx.x;
    int orig = (n < NG) ? ((n & 3) * HID + (n >> 2)) : 0;
    __half* dst = g_Wh2 + (size_t)n * KH2;
    const float* src = Whh + (size_t)orig * HID;
    for (int k = threadIdx.x; k < HID; k += 256) {
        __half hi = __float2half_rn((n < NG) ? src[k] : 0.f);
        dst[k] = hi; dst[HID + k] = hi;
    }
    if (threadIdx.x < KH2 - 2 * HID) dst[2 * HID + threadIdx.x] = __float2half(0.f);
}

// ---------------- big GEMM: G0(perm, padded) = V2 @ W2^T + bias ----------------
__global__ __launch_bounds__(256) void k_bigmma(const float* __restrict__ bih,
                                                const float* __restrict__ bhh)
{
    extern __shared__ char smem[];
    uint32_t sbuf = smem_u32(smem);
    float* stage = (float*)smem;
    __shared__ float biasS[128];
    int tid = threadIdx.x;
    int lane = tid & 31, wm = (tid >> 5) & 3, wn = tid >> 7;
    int bn = blockIdx.x, bm = blockIdx.y;

    if (tid < 128) {
        int np = bn * 128 + tid;
        biasS[tid] = (np < NG) ? (bih[(np & 3) * HID + (np >> 2)] + bhh[(np & 3) * HID + (np >> 2)]) : 0.f;
    }

    float acc[2][8][4];
    #pragma unroll
    for (int a = 0; a < 2; a++)
        #pragma unroll
        for (int b = 0; b < 8; b++)
            #pragma unroll
            for (int c = 0; c < 4; c++) acc[a][b][c] = 0.f;

    gemm_mainloop(g_V2 + (size_t)(bm * 128) * K2, g_W2 + (size_t)(bn * 128) * K2,
                  K2, K2, NCBIG, sbuf, acc, tid);

    #pragma unroll
    for (int nh = 0; nh < 2; nh++) {
        if (wn == nh) stage_pass(stage, acc, lane, wm);
        __syncthreads();
        #pragma unroll
        for (int i = 0; i < 8; i++) {
            int lin = tid + i * 256;
            int r = lin >> 4, c4 = lin & 15;
            int col = nh * 64 + c4 * 4;
            float4 v;
            v.x = stage[r * 66 + c4 * 4 + 0] + biasS[col + 0];
            v.y = stage[r * 66 + c4 * 4 + 1] + biasS[col + 1];
            v.z = stage[r * 66 + c4 * 4 + 2] + biasS[col + 2];
            v.w = stage[r * 66 + c4 * 4 + 3] + biasS[col + 3];
            *(float4*)&g_G0[(size_t)(bm * 128 + r) * NGP + bn * 128 + col] = v;
        }
        __syncthreads();
    }
}

// ---------------- recurrent GEMM + imputation prologue + fused LSTM cell ----------------
__global__ __launch_bounds__(256) void k_gates(
    const float* __restrict__ V, const float* __restrict__ Wih,
    const float* __restrict__ masks, const float* __restrict__ deltas,
    const float* __restrict__ bdec, const float* __restrict__ Wreg,
    const float* __restrict__ breg, float* __restrict__ outImp, int t)
{
    extern __shared__ char smem[];
    uint32_t sbuf = smem_u32(smem);
    float* stage = (float*)smem;
    __shared__ float wvS[128], wmS[128];
    __shared__ float wsumS[32], bdecS[32], wregS[32];
    __shared__ float alphaS[128], mS[128];
    __shared__ float lossRed[2];
    int tid = threadIdx.x;
    int lane = tid & 31, wm = (tid >> 5) & 3, wn = tid >> 7;
    int bn = blockIdx.x, bm = blockIdx.y;
    int par = t & 1;

    if (tid < 128) {
        int np = bn * 128 + tid;
        if (np < NG) {
            size_t grow = (size_t)((np & 3) * HID + (np >> 2)) * (NF + 1);
            wvS[tid] = Wih[grow + (NF - 1)];
            wmS[tid] = Wih[grow + NF];
        } else { wvS[tid] = 0.f; wmS[tid] = 0.f; }
    }
    if (tid >= 128 && tid < 160) {
        int jl = tid - 128;
        int j = bn * 32 + jl;
        wsumS[jl] = (j < HID) ? g_wsum[j] : 0.f;
        bdecS[jl] = (j < HID) ? bdec[j] : 0.f;
        wregS[jl] = (j < HID) ? Wreg[j] : 0.f;
    }
    if (tid == 0) { lossRed[0] = 0.f; lossRed[1] = 0.f; }

    // ---- prologue: per-row regression xh, imputation, alpha, loss ----
    {
        float nloc = 0.f, dloc = 0.f;
        if (tid < 128) {
            int b = bm * 128 + tid;
            float xh = breg[0];
            #pragma unroll
            for (int p = 0; p < NBT; p++) xh += g_xh_part[par][p][b];
            float m  = masks[b * T_SEQ + t];
            float v  = V[((size_t)b * T_SEQ + t) * NF + (NF - 1)];
            float xvar = v * m + (1.f - m) * xh;
            alphaS[tid] = xvar - v;
            mS[tid] = m;
            if (bn == 0) {
                outImp[b * T_SEQ + t] = xvar;
                nloc = fabsf(xvar - xh) * m;
                dloc = m;
            }
        }
        if (bn == 0) {
            #pragma unroll
            for (int off = 16; off; off >>= 1) {
                nloc += __shfl_xor_sync(0xffffffff, nloc, off);
                dloc += __shfl_xor_sync(0xffffffff, dloc, off);
            }
            if (tid < 128 && (tid & 31) == 0) {
                atomicAdd(&lossRed[0], nloc);
                atomicAdd(&lossRed[1], dloc);
            }
        }
    }
    __syncthreads();
    if (bn == 0 && tid == 0) {
        atomicAdd(&g_num[t], lossRed[0]);
        atomicAdd(&g_den[t], lossRed[1]);
    }

    float acc[2][8][4];
    #pragma unroll
    for (int a = 0; a < 2; a++)
        #pragma unroll
        for (int b = 0; b < 8; b++)
            #pragma unroll
            for (int c = 0; c < 4; c++) acc[a][b][c] = 0.f;

    gemm_mainloop(g_h2[par] + (size_t)(bm * 128) * KH2, g_Wh2 + (size_t)(bn * 128) * KH2,
                  KH2, KH2, NCGAT, sbuf, acc, tid);

    __half* h2n = g_h2[1 - par];
    bool more = (t + 1 < T_SEQ);
    float xh_i[8];
    #pragma unroll
    for (int i = 0; i < 8; i++) xh_i[i] = 0.f;

    #pragma unroll
    for (int nh = 0; nh < 2; nh++) {
        if (wn == nh) stage_pass(stage, acc, lane, wm);
        __syncthreads();
        #pragma unroll
        for (int i = 0; i < 8; i++) {
            int lin = tid + i * 256;       // 128 rows x 16 jl
            int r = lin >> 4, jl = lin & 15;
            int b = bm * 128 + r;
            int j = bn * 32 + nh * 16 + jl;
            float alpha = alphaS[r];
            float m = mS[r];
            int nl = nh * 64 + jl * 4;
            float4 g0 = *(const float4*)&g_G0[((size_t)b * T_SEQ + t) * NGP + bn * 128 + nl];
            float ig = stage[r * 66 + jl * 4 + 0] + g0.x + alpha * wvS[nl + 0] + m * wmS[nl + 0];
            float fg = stage[r * 66 + jl * 4 + 1] + g0.y + alpha * wvS[nl + 1] + m * wmS[nl + 1];
            float gg = stage[r * 66 + jl * 4 + 2] + g0.z + alpha * wvS[nl + 2] + m * wmS[nl + 2];
            float og = stage[r * 66 + jl * 4 + 3] + g0.w + alpha * wvS[nl + 3] + m * wmS[nl + 3];
            float contrib = 0.f;
            if (j < HID) {
                float si = 1.f / (1.f + expf(-ig));
                float sf = 1.f / (1.f + expf(-fg));
                float so = 1.f / (1.f + expf(-og));
                float tg = tanhf(gg);
                size_t ci = (size_t)b * HID + j;
                float c = sf * g_c[ci] + si * tg;
                g_c[ci] = c;
                float hnew = so * tanhf(c);
                if (more) {
                    float dnx = deltas[b * T_SEQ + t + 1];
                    float wdc = fmaf(dnx, wsumS[nh * 16 + jl], bdecS[nh * 16 + jl]);
                    float gamma = expf(-fmaxf(wdc, 0.f));
                    float hv = hnew * gamma;
                    __half hi = __float2half_rn(hv);
                    __half lo = __float2half_rn(hv - __half2float(hi));
                    h2n[(size_t)b * KH2 + j] = hi;
                    h2n[(size_t)b * KH2 + HID + j] = lo;
                    contrib = hv * wregS[nh * 16 + jl];
                }
            }
            #pragma unroll
            for (int off = 8; off; off >>= 1)
                contrib += __shfl_xor_sync(0xffffffff, contrib, off);
            if ((tid & 15) == 0) xh_i[i] += contrib;
        }
        __syncthreads();
    }

    if (more && (tid & 15) == 0) {
        #pragma unroll
        for (int i = 0; i < 8; i++) {
            int b = bm * 128 + ((tid + i * 256) >> 4);
            g_xh_part[1 - par][bn][b] = xh_i[i];   // (b, bn) owned by this block
        }
    }
}

// ---------------- finalize loss ----------------
__global__ void k_final(float* __restrict__ out) {
    if (threadIdx.x == 0) {
        float s = 0.f;
        for (int tt = 0; tt < T_SEQ; tt++) s += g_num[tt] / (g_den[tt] + 1e-5f);
        out[0] = s / (float)T_SEQ;
    }
}

extern "C" void kernel_launch(void* const* d_in, const int* in_sizes, int n_in,
                              void* d_out, int out_size)
{
    const float* V      = (const float*)d_in[0];
    const float* masks  = (const float*)d_in[1];
    const float* deltas = (const float*)d_in[2];
    const float* Wdec   = (const float*)d_in[3];
    const float* bdec   = (const float*)d_in[4];
    const float* Wreg   = (const float*)d_in[5];
    const float* breg   = (const float*)d_in[6];
    const float* Wih    = (const float*)d_in[7];
    const float* Whh    = (const float*)d_in[8];
    const float* bih    = (const float*)d_in[9];
    const float* bhh    = (const float*)d_in[10];
    float* out = (float*)d_out;

    k_init<<<2048, 256>>>();
    k_wsum<<<HID, 256>>>(Wdec);

    k_convV<<<MROWS, 256>>>(V);
    k_convW<<<NGP, 256>>>(Wih);
    k_convWh<<<NGP, 256>>>(Whh);

    dim3 gB(NBT, MROWS / 128);     // (13, 1280); bn fastest -> A tile L2 reuse
    k_bigmma<<<gB, 256, SMEM_DYN>>>(bih, bhh);

    for (int t = 0; t < T_SEQ; t++) {
        dim3 g4(NBT, BATCH / 128); // (13, 64)
        k_gates<<<g4, 256, SMEM_DYN>>>(V, Wih, masks, deltas, bdec, Wreg, breg, out + 1, t);
    }
    k_final<<<1, 32>>>(out);
}

// round 7
// speedup vs baseline: 1.4786x; 1.4786x over previous
#include <cuda_runtime.h>
#include <cuda_fp16.h>
#include <math.h>
#include <stdint.h>

#define T_SEQ 20
#define NF    812
#define HID   400
#define NG    1600            // 4*HID
#define BATCH 8192
#define MROWS (BATCH * T_SEQ) // 163840
#define KP    832             // per-section K big GEMM (26*32)
#define K2    (2 * KP)        // 1664: [hi(V), lo(V)] exact split
#define KH2   832             // gates K: [hi(400), lo(400), pad 32]
#define NCBIG (K2 / 32)       // 52
#define NCGAT (KH2 / 32)      // 26
#define NBN   (NG / 64)       // 25 n-tiles

// ---------------- device scratch ----------------
__device__ __half g_V2[(size_t)MROWS * K2];          // ~545 MB split values
__device__ __half g_W2[(size_t)NG * K2];             // W_ih [hi,hi] perm rows
__device__ __half g_Wh2[(size_t)NG * KH2];           // W_hh [hi,hi] perm rows
__device__ __half g_h2[2][(size_t)BATCH * KH2];      // [hi(h), lo(h)] decayed h (dbl buf)
__device__ float g_G0[(size_t)MROWS * NG];           // ~1.05 GB perm gate pre-acts
__device__ float g_c [BATCH * HID];
__device__ float g_xh_part[2][NBN][BATCH];           // per-bn regression partials (dbl buf)
__device__ float g_wsum[HID];
__device__ float g_num[T_SEQ];
__device__ float g_den[T_SEQ];

// ---------------- PTX helpers ----------------
__device__ __forceinline__ uint32_t smem_u32(const void* p) {
    uint32_t a;
    asm("{ .reg .u64 t; cvta.to.shared.u64 t, %1; cvt.u32.u64 %0, t; }" : "=r"(a) : "l"(p));
    return a;
}
__device__ __forceinline__ void cp_async16(uint32_t saddr, const void* gaddr) {
    asm volatile("cp.async.cg.shared.global [%0], [%1], 16;\n" :: "r"(saddr), "l"(gaddr) : "memory");
}
__device__ __forceinline__ void ldsm_x4(uint32_t* r, uint32_t addr) {
    asm volatile("ldmatrix.sync.aligned.m8n8.x4.shared.b16 {%0,%1,%2,%3}, [%4];"
                 : "=r"(r[0]), "=r"(r[1]), "=r"(r[2]), "=r"(r[3]) : "r"(addr));
}
__device__ __forceinline__ void mma16816(float* d, const uint32_t* a, const uint32_t* b) {
    asm volatile(
        "mma.sync.aligned.m16n8k16.row.col.f32.f16.f16.f32 "
        "{%0,%1,%2,%3}, {%4,%5,%6,%7}, {%8,%9}, {%0,%1,%2,%3};"
        : "+f"(d[0]), "+f"(d[1]), "+f"(d[2]), "+f"(d[3])
        : "r"(a[0]), "r"(a[1]), "r"(a[2]), "r"(a[3]), "r"(b[0]), "r"(b[1]));
}

// smem: A 128 rows x 32 halves (80B stride), B 64 rows x 32 halves
#define A_STRIDE_B 80
#define A_TILE_B   (128 * A_STRIDE_B)    // 10240
#define B_TILE_B   (64 * A_STRIDE_B)     // 5120
#define BUF_B      (A_TILE_B + B_TILE_B) // 15360 per stage
#define NSTAGE     3
#define SMEM_DYN   (NSTAGE * BUF_B)      // 46080 (<48K); epilogue stage 33792 fits

// ---------------- mma mainloop (BM=128, BN=64, BK=32, 8 warps 4x2, 3-stage) --------
__device__ __forceinline__ void gemm_mainloop(
    const __half* Abase, const __half* Bbase,
    int aStride, int bStride, int nChunks,
    uint32_t sbuf, float acc[2][4][4], int tid)
{
    int lane = tid & 31, w = tid >> 5;
    int wm = w & 3, wn = w >> 2;
    uint32_t aOffBase = (uint32_t)((wm * 32 + (lane & 15)) * A_STRIDE_B + ((lane >> 4) << 4));
    uint32_t bOffBase = (uint32_t)(A_TILE_B +
        (wn * 32 + ((lane >> 4) << 3) + (lane & 7)) * A_STRIDE_B + (((lane >> 3) & 1) << 4));

    int lrow = tid >> 2, lseg = tid & 3;

    // preload chunks 0 and 1
    #pragma unroll
    for (int pc = 0; pc < 2; pc++) {
        uint32_t dst = sbuf + pc * BUF_B;
        int koff = pc * 32;
        cp_async16(dst + lrow * A_STRIDE_B + lseg * 16,
                   Abase + (size_t)lrow * aStride + koff + lseg * 8);
        cp_async16(dst + (lrow + 64) * A_STRIDE_B + lseg * 16,
                   Abase + (size_t)(lrow + 64) * aStride + koff + lseg * 8);
        cp_async16(dst + A_TILE_B + lrow * A_STRIDE_B + lseg * 16,
                   Bbase + (size_t)lrow * bStride + koff + lseg * 8);
        asm volatile("cp.async.commit_group;\n" ::: "memory");
    }

    int bufc = 0;   // c % 3
    int bufn = 2;   // (c+2) % 3
    for (int c = 0; c < nChunks; c++) {
        if (c + 1 < nChunks) {
            asm volatile("cp.async.wait_group 1;\n" ::: "memory");
        } else {
            asm volatile("cp.async.wait_group 0;\n" ::: "memory");
        }
        __syncthreads();

        if (c + 2 < nChunks) {
            uint32_t dst = sbuf + bufn * BUF_B;
            int koff = (c + 2) * 32;
            cp_async16(dst + lrow * A_STRIDE_B + lseg * 16,
                       Abase + (size_t)lrow * aStride + koff + lseg * 8);
            cp_async16(dst + (lrow + 64) * A_STRIDE_B + lseg * 16,
                       Abase + (size_t)(lrow + 64) * aStride + koff + lseg * 8);
            cp_async16(dst + A_TILE_B + lrow * A_STRIDE_B + lseg * 16,
                       Bbase + (size_t)lrow * bStride + koff + lseg * 8);
            asm volatile("cp.async.commit_group;\n" ::: "memory");
        }

        uint32_t cur = sbuf + bufc * BUF_B;
        #pragma unroll
        for (int kc = 0; kc < 2; kc++) {
            uint32_t aregs[2][4], bregs[2][4];
            ldsm_x4(aregs[0], cur + aOffBase + kc * 32);
            ldsm_x4(aregs[1], cur + aOffBase + 16 * A_STRIDE_B + kc * 32);
            ldsm_x4(bregs[0], cur + bOffBase + kc * 32);
            ldsm_x4(bregs[1], cur + bOffBase + 16 * A_STRIDE_B + kc * 32);
            #pragma unroll
            for (int mi = 0; mi < 2; mi++)
                #pragma unroll
                for (int ni = 0; ni < 4; ni++)
                    mma16816(acc[mi][ni], aregs[mi], &bregs[ni >> 1][(ni & 1) * 2]);
        }
        bufc = (bufc == 2) ? 0 : bufc + 1;
        bufn = (bufn == 2) ? 0 : bufn + 1;
    }
    __syncthreads();  // protect smem before epilogue staging reuses it
}

// stage acc -> smem fp32 [128][66]
__device__ __forceinline__ void stage_acc(float* stage, float acc[2][4][4], int tid) {
    int lane = tid & 31, w = tid >> 5;
    int wm = w & 3, wn = w >> 2;
    #pragma unroll
    for (int mi = 0; mi < 2; mi++)
        #pragma unroll
        for (int ni = 0; ni < 4; ni++) {
            int r0 = wm * 32 + mi * 16 + (lane >> 2);
            int cc = wn * 32 + ni * 8 + (lane & 3) * 2;
            *(float2*)&stage[r0 * 66 + cc]       = make_float2(acc[mi][ni][0], acc[mi][ni][1]);
            *(float2*)&stage[(r0 + 8) * 66 + cc] = make_float2(acc[mi][ni][2], acc[mi][ni][3]);
        }
}

// ---------------- init ----------------
__global__ void k_init() {
    long i = (long)blockIdx.x * blockDim.x + threadIdx.x;
    long stride = (long)gridDim.x * blockDim.x;
    for (long p = i; p < (long)BATCH * HID; p += stride) g_c[p] = 0.f;
    for (long p = i; p < 2L * BATCH * KH2; p += stride) ((__half*)g_h2)[p] = __float2half(0.f);
    for (long p = i; p < 2L * NBN * BATCH; p += stride) ((float*)g_xh_part)[p] = 0.f;
    if (i < T_SEQ) { g_num[i] = 0.f; g_den[i] = 0.f; }
}

// ---------------- w_sum ----------------
__global__ void k_wsum(const float* __restrict__ Wd) {
    int row = blockIdx.x;
    __shared__ float red[256];
    float s = 0.f;
    for (int k = threadIdx.x; k < NF; k += 256) s += Wd[(size_t)row * NF + k];
    red[threadIdx.x] = s;
    __syncthreads();
    for (int off = 128; off; off >>= 1) {
        if (threadIdx.x < off) red[threadIdx.x] += red[threadIdx.x + off];
        __syncthreads();
    }
    if (threadIdx.x == 0) g_wsum[row] = red[0];
}

// ---------------- V2 = [hi(V), lo(V)] (exact split) ----------------
__global__ void k_convV(const float* __restrict__ V) {
    int r = blockIdx.x;
    const float* src = V + (size_t)r * NF;
    __half* dst = g_V2 + (size_t)r * K2;
    for (int k = threadIdx.x; k < KP; k += 256) {
        float v = (k < NF) ? src[k] : 0.f;
        __half hi = __float2half_rn(v);
        __half lo = __float2half_rn(v - __half2float(hi));
        dst[k] = hi; dst[KP + k] = lo;
    }
}

// ---------------- W2 rows permuted (n = j*4+g), [hi, hi] ----------------
__global__ void k_convW(const float* __restrict__ Wih) {
    int n = blockIdx.x;
    int orig = (n & 3) * HID + (n >> 2);
    __half* dst = g_W2 + (size_t)n * K2;
    const float* src = Wih + (size_t)orig * (NF + 1);
    for (int k = threadIdx.x; k < KP; k += 256) {
        float w = (k < NF) ? src[k] : 0.f;
        __half hi = __float2half_rn(w);
        dst[k] = hi; dst[KP + k] = hi;
    }
}

// ---------------- Wh2 rows permuted, [hi(400), hi(400), pad 0] ----------------
__global__ void k_convWh(const float* __restrict__ Whh) {
    int n = blockIdx.x;
    int orig = (n & 3) * HID + (n >> 2);
    __half* dst = g_Wh2 + (size_t)n * KH2;
    const float* src = Whh + (size_t)orig * HID;
    for (int k = threadIdx.x; k < HID; k += 256) {
        __half hi = __float2half_rn(src[k]);
        dst[k] = hi; dst[HID + k] = hi;
    }
    if (threadIdx.x < KH2 - 2 * HID) dst[2 * HID + threadIdx.x] = __float2half(0.f);
}

// ---------------- big GEMM: G0(perm) = V2 @ W2^T + bias ----------------
__global__ __launch_bounds__(256) void k_bigmma(const float* __restrict__ bih,
                                                const float* __restrict__ bhh)
{
    extern __shared__ char smem[];
    uint32_t sbuf = smem_u32(smem);
    float* stage = (float*)smem;
    __shared__ float biasS[64];
    int tid = threadIdx.x;
    int bn = blockIdx.x, bm = blockIdx.y;

    if (tid < 64) {
        int np = bn * 64 + tid;
        int orig = (np & 3) * HID + (np >> 2);
        biasS[tid] = bih[orig] + bhh[orig];
    }

    float acc[2][4][4];
    #pragma unroll
    for (int a = 0; a < 2; a++)
        #pragma unroll
        for (int b = 0; b < 4; b++)
            #pragma unroll
            for (int c = 0; c < 4; c++) acc[a][b][c] = 0.f;

    gemm_mainloop(g_V2 + (size_t)(bm * 128) * K2, g_W2 + (size_t)(bn * 64) * K2,
                  K2, K2, NCBIG, sbuf, acc, tid);

    stage_acc(stage, acc, tid);
    __syncthreads();

    #pragma unroll
    for (int i = 0; i < 8; i++) {
        int lin = tid + i * 256;
        int r = lin >> 4, c4 = lin & 15;
        float4 v;
        v.x = stage[r * 66 + c4 * 4 + 0] + biasS[c4 * 4 + 0];
        v.y = stage[r * 66 + c4 * 4 + 1] + biasS[c4 * 4 + 1];
        v.z = stage[r * 66 + c4 * 4 + 2] + biasS[c4 * 4 + 2];
        v.w = stage[r * 66 + c4 * 4 + 3] + biasS[c4 * 4 + 3];
        *(float4*)&g_G0[(size_t)(bm * 128 + r) * NG + bn * 64 + c4 * 4] = v;
    }
}

// ---------------- recurrent GEMM + imputation prologue + fused LSTM cell ----------------
__global__ __launch_bounds__(256) void k_gates(
    const float* __restrict__ V, const float* __restrict__ Wih,
    const float* __restrict__ masks, const float* __restrict__ deltas,
    const float* __restrict__ bdec, const float* __restrict__ Wreg,
    const float* __restrict__ breg, float* __restrict__ outImp, int t)
{
    extern __shared__ char smem[];
    uint32_t sbuf = smem_u32(smem);
    float* stage = (float*)smem;
    __shared__ float wvS[64], wmS[64];
    __shared__ float wsumS[16], bdecS[16], wregS[16];
    __shared__ float alphaS[128], mS[128];
    __shared__ float lossRed[2];
    int tid = threadIdx.x;
    int bn = blockIdx.x, bm = blockIdx.y;
    int par = t & 1;

    if (tid < 64) {
        int np = bn * 64 + tid;
        int orig = (np & 3) * HID + (np >> 2);
        wvS[tid] = Wih[(size_t)orig * (NF + 1) + (NF - 1)];
        wmS[tid] = Wih[(size_t)orig * (NF + 1) + NF];
    }
    if (tid >= 64 && tid < 80) {
        int jl = tid - 64;
        int j = bn * 16 + jl;
        wsumS[jl] = g_wsum[j];
        bdecS[jl] = bdec[j];
        wregS[jl] = Wreg[j];
    }
    if (tid == 0) { lossRed[0] = 0.f; lossRed[1] = 0.f; }

    // ---- prologue: per-row regression xh, imputation, alpha, loss ----
    {
        float nloc = 0.f, dloc = 0.f;
        if (tid < 128) {
            int b = bm * 128 + tid;
            float xh = breg[0];
            #pragma unroll
            for (int p = 0; p < NBN; p++) xh += g_xh_part[par][p][b];
            float m  = masks[b * T_SEQ + t];
            float v  = V[((size_t)b * T_SEQ + t) * NF + (NF - 1)];
            float xvar = v * m + (1.f - m) * xh;
            alphaS[tid] = xvar - v;
            mS[tid] = m;
            if (bn == 0) {
                outImp[b * T_SEQ + t] = xvar;
                nloc = fabsf(xvar - xh) * m;
                dloc = m;
            }
        }
        if (bn == 0) {
            #pragma unroll
            for (int off = 16; off; off >>= 1) {
                nloc += __shfl_xor_sync(0xffffffff, nloc, off);
                dloc += __shfl_xor_sync(0xffffffff, dloc, off);
            }
            if (tid < 128 && (tid & 31) == 0) {
                atomicAdd(&lossRed[0], nloc);
                atomicAdd(&lossRed[1], dloc);
            }
        }
    }
    __syncthreads();
    if (bn == 0 && tid == 0) {
        atomicAdd(&g_num[t], lossRed[0]);
        atomicAdd(&g_den[t], lossRed[1]);
    }

    float acc[2][4][4];
    #pragma unroll
    for (int a = 0; a < 2; a++)
        #pragma unroll
        for (int b = 0; b < 4; b++)
            #pragma unroll
            for (int c = 0; c < 4; c++) acc[a][b][c] = 0.f;

    gemm_mainloop(g_h2[par] + (size_t)(bm * 128) * KH2, g_Wh2 + (size_t)(bn * 64) * KH2,
                  KH2, KH2, NCGAT, sbuf, acc, tid);

    stage_acc(stage, acc, tid);
    __syncthreads();

    __half* h2n = g_h2[1 - par];
    bool more = (t + 1 < T_SEQ);
    float xh_i[8];
    #pragma unroll
    for (int i = 0; i < 8; i++) xh_i[i] = 0.f;

    #pragma unroll
    for (int i = 0; i < 8; i++) {
        int lin = tid + i * 256;       // 128 rows x 16 jl
        int r = lin >> 4, jl = lin & 15;
        int b = bm * 128 + r;
        float alpha = alphaS[r];
        float m = mS[r];
        int c0 = jl * 4;
        float4 g0 = *(const float4*)&g_G0[((size_t)b * T_SEQ + t) * NG + bn * 64 + c0];
        float ig = stage[r * 66 + c0 + 0] + g0.x + alpha * wvS[c0 + 0] + m * wmS[c0 + 0];
        float fg = stage[r * 66 + c0 + 1] + g0.y + alpha * wvS[c0 + 1] + m * wmS[c0 + 1];
        float gg = stage[r * 66 + c0 + 2] + g0.z + alpha * wvS[c0 + 2] + m * wmS[c0 + 2];
        float og = stage[r * 66 + c0 + 3] + g0.w + alpha * wvS[c0 + 3] + m * wmS[c0 + 3];
        float si = 1.f / (1.f + expf(-ig));
        float sf = 1.f / (1.f + expf(-fg));
        float so = 1.f / (1.f + expf(-og));
        float tg = tanhf(gg);
        int j = bn * 16 + jl;
        size_t ci = (size_t)b * HID + j;
        float c = sf * g_c[ci] + si * tg;
        g_c[ci] = c;
        float hnew = so * tanhf(c);

        float contrib = 0.f;
        if (more) {
            float dnx = deltas[b * T_SEQ + t + 1];
            float wdc = fmaf(dnx, wsumS[jl], bdecS[jl]);
            float gamma = expf(-fmaxf(wdc, 0.f));
            float hv = hnew * gamma;
            __half hi = __float2half_rn(hv);
            __half lo = __float2half_rn(hv - __half2float(hi));
            h2n[(size_t)b * KH2 + j] = hi;
            h2n[(size_t)b * KH2 + HID + j] = lo;
            contrib = hv * wregS[jl];
        }
        #pragma unroll
        for (int off = 8; off; off >>= 1)
            contrib += __shfl_xor_sync(0xffffffff, contrib, off);
        if ((tid & 15) == 0) xh_i[i] = contrib;
    }

    if (more && (tid & 15) == 0) {
        #pragma unroll
        for (int i = 0; i < 8; i++) {
            int b = bm * 128 + ((tid + i * 256) >> 4);
            g_xh_part[1 - par][bn][b] = xh_i[i];   // (b, bn) owned by this block
        }
    }
}

// ---------------- finalize loss ----------------
__global__ void k_final(float* __restrict__ out) {
    if (threadIdx.x == 0) {
        float s = 0.f;
        for (int tt = 0; tt < T_SEQ; tt++) s += g_num[tt] / (g_den[tt] + 1e-5f);
        out[0] = s / (float)T_SEQ;
    }
}

extern "C" void kernel_launch(void* const* d_in, const int* in_sizes, int n_in,
                              void* d_out, int out_size)
{
    const float* V      = (const float*)d_in[0];
    const float* masks  = (const float*)d_in[1];
    const float* deltas = (const float*)d_in[2];
    const float* Wdec   = (const float*)d_in[3];
    const float* bdec   = (const float*)d_in[4];
    const float* Wreg   = (const float*)d_in[5];
    const float* breg   = (const float*)d_in[6];
    const float* Wih    = (const float*)d_in[7];
    const float* Whh    = (const float*)d_in[8];
    const float* bih    = (const float*)d_in[9];
    const float* bhh    = (const float*)d_in[10];
    float* out = (float*)d_out;

    k_init<<<2048, 256>>>();
    k_wsum<<<HID, 256>>>(Wdec);

    k_convV<<<MROWS, 256>>>(V);
    k_convW<<<NG, 256>>>(Wih);
    k_convWh<<<NG, 256>>>(Whh);

    dim3 gB(NBN, MROWS / 128);     // (25, 1280); bn fastest -> A tile L2 reuse
    k_bigmma<<<gB, 256, SMEM_DYN>>>(bih, bhh);

    for (int t = 0; t < T_SEQ; t++) {
        dim3 g4(NBN, BATCH / 128); // (25, 64)
        k_gates<<<g4, 256, SMEM_DYN>>>(V, Wih, masks, deltas, bdec, Wreg, breg, out + 1, t);
    }
    k_final<<<1, 32>>>(out);
}